// round 13
// baseline (speedup 1.0000x reference)
#include <cuda_runtime.h>

// ---------------------------------------------------------------------------
// TimeAggNet fused pipeline, fp32 with packed f32x2 FMA (2 samples per thread)
// ---------------------------------------------------------------------------

#define BS   256
#define NN   128
#define BN   (BS*NN)      // 32768 samples
#define TLEN 1216
#define C1   32
#define P1L  30
#define C2   64
#define L2C  10
#define C3   128
#define K3   256          // C2 * 4
#define XP   42           // padded per-position window pitch (float2 units)

typedef unsigned long long ull;

// packed-weight scratch (duplicated {w,w} for f32x2 broadcast)
__device__ __align__(16) float2 g_w1d[C1*10];
__device__ __align__(16) float2 g_b1d[C1];
__device__ __align__(16) float2 g_w2td[96*C2];   // [ci*3+k][co], dup-packed
__device__ __align__(16) float2 g_b2d[C2];
// stage1 weights on the constant port (filled via captured D2D memcpy)
__constant__ __align__(16) float2 c_w1[C1*10];
__constant__ __align__(16) float2 c_b1[C1];
// activations scratch
__device__ __align__(16) float2 g_h2[(BN/2)*K3]; // [pair q][j]
__device__ __align__(16) float  g_h3[(size_t)BN*C3];
__device__ float  g_part[BS][8][3];

__device__ __forceinline__ ull pk2(float a, float b) {
    ull r; asm("mov.b64 %0,{%1,%2};" : "=l"(r) : "f"(a), "f"(b)); return r;
}
__device__ __forceinline__ float2 upk(ull v) {
    float a, b; asm("mov.b64 {%0,%1},%2;" : "=f"(a), "=f"(b) : "l"(v));
    return make_float2(a, b);
}
__device__ __forceinline__ ull ffma2(ull a, ull b, ull c) {
    ull d; asm("fma.rn.f32x2 %0,%1,%2,%3;" : "=l"(d) : "l"(a), "l"(b), "l"(c));
    return d;
}
__device__ __forceinline__ ull addx2(ull a, ull b) {
    ull d; asm("add.rn.f32x2 %0,%1,%2;" : "=l"(d) : "l"(a), "l"(b));
    return d;
}

// ---------------------------------------------------------------------------
__global__ void setup_pack(const float* __restrict__ w1, const float* __restrict__ b1,
                           const float* __restrict__ w2, const float* __restrict__ b2) {
    int t = blockIdx.x * blockDim.x + threadIdx.x;
    if (t < C1*10) { float v = w1[t]; g_w1d[t] = make_float2(v, v); }
    if (t < C1)    { float v = b1[t]; g_b1d[t] = make_float2(v, v); }
    if (t < C2)    { float v = b2[t]; g_b2d[t] = make_float2(v, v); }
    if (t < 96*C2) {                       // transpose w2 [co][ci*3+k] -> [j][co]
        int j = t >> 6, co = t & 63;
        float v = w2[co*96 + j];
        g_w2td[t] = make_float2(v, v);
    }
}

// empty kernels to shift ncu's fixed "-s 5 -c 1" capture window onto stage12
__global__ void dummyk() {}

// ---------------------------------------------------------------------------
// stage12: one block per sample pair, 128 threads, 6 blocks/SM.
// stage1 x windows stored PRIVATELY per position with pitch 42 float2:
// bank stride 84 % 32 = 20 -> conflict-free LDS.128 across lanes.
__global__ __launch_bounds__(128, 6) void stage12(const float* __restrict__ x) {
    __shared__ __align__(16) union SU {
        float2 xs[P1L*XP];            // [pos][z]: x[40*pos - 1 + z]; 10080 B
        ull red[2][20][32];           // 10240 B
    } u;
    __shared__ __align__(16) float2 p1s[C1*P1L];     // 7680 B
    __shared__ __align__(16) float2 c2s[C2*11];      // pitch 11: 5632 B

    const int q   = blockIdx.x;
    const int tid = threadIdx.x;
    const float* xA = x + (size_t)(2*q) * TLEN;
    const float* xB = xA + TLEN;

    // staging: lane-consecutive writes (2 wavefronts/STS), coalesced LDG.32
    for (int i = tid; i < P1L*XP; i += 128) {
        const int p = i / XP;                 // position
        const int m = i - 2*p - 1;            // = 40p - 1 + (i - 42p)
        float a = 0.f, b = 0.f;
        if (m >= 0) { a = xA[m]; b = xB[m]; }
        u.xs[i] = make_float2(a, b);
    }
    __syncthreads();

    // ---- stage 1: conv1 + relu + pool5, three-phase; weights via const port
    {
        const int pos = tid & 31, cg = tid >> 5;
        if (pos < P1L) {
            const float2* xw = &u.xs[XP*pos];
            // phase 0: windows j=0,1 (z 0..17)
            {
                ull r[18];
                const ulonglong2* bp = (const ulonglong2*)xw;
                #pragma unroll
                for (int z = 0; z < 9; z++) {
                    ulonglong2 v = bp[z]; r[2*z] = v.x; r[2*z+1] = v.y;
                }
                #pragma unroll 1
                for (int cc = 0; cc < 8; cc++) {
                    const int c = cg*8 + cc;
                    ull w[10];
                    #pragma unroll
                    for (int m = 0; m < 5; m++) {
                        ulonglong2 wv = *(const ulonglong2*)&c_w1[c*10 + 2*m];
                        w[2*m] = wv.x; w[2*m+1] = wv.y;
                    }
                    ull a0 = 0ull, a1 = 0ull;
                    #pragma unroll
                    for (int k = 0; k < 10; k++) {
                        a0 = ffma2(r[k],     w[k], a0);
                        a1 = ffma2(r[8 + k], w[k], a1);
                    }
                    float2 s0 = upk(a0), s1 = upk(a1);
                    p1s[c*P1L + pos] = make_float2(fmaxf(s0.x, s1.x),
                                                   fmaxf(s0.y, s1.y));
                }
            }
            // phase 1: windows j=2,3 (z 16..33)
            {
                ull r[18];
                const ulonglong2* bp = (const ulonglong2*)(xw + 16);
                #pragma unroll
                for (int z = 0; z < 9; z++) {
                    ulonglong2 v = bp[z]; r[2*z] = v.x; r[2*z+1] = v.y;
                }
                #pragma unroll 1
                for (int cc = 0; cc < 8; cc++) {
                    const int c = cg*8 + cc;
                    ull w[10];
                    #pragma unroll
                    for (int m = 0; m < 5; m++) {
                        ulonglong2 wv = *(const ulonglong2*)&c_w1[c*10 + 2*m];
                        w[2*m] = wv.x; w[2*m+1] = wv.y;
                    }
                    ull a0 = 0ull, a1 = 0ull;
                    #pragma unroll
                    for (int k = 0; k < 10; k++) {
                        a0 = ffma2(r[k],     w[k], a0);   // window 2
                        a1 = ffma2(r[8 + k], w[k], a1);   // window 3
                    }
                    float2 s0 = upk(a0), s1 = upk(a1);
                    float2 pm = p1s[c*P1L + pos];
                    p1s[c*P1L + pos] =
                        make_float2(fmaxf(pm.x, fmaxf(s0.x, s1.x)),
                                    fmaxf(pm.y, fmaxf(s0.y, s1.y)));
                }
            }
            // phase 2: window j=4 (z 32..41), + bias + relu
            {
                ull r[10];
                const ulonglong2* bp = (const ulonglong2*)(xw + 32);
                #pragma unroll
                for (int z = 0; z < 5; z++) {
                    ulonglong2 v = bp[z]; r[2*z] = v.x; r[2*z+1] = v.y;
                }
                #pragma unroll 1
                for (int cc = 0; cc < 8; cc++) {
                    const int c = cg*8 + cc;
                    ull w[10];
                    #pragma unroll
                    for (int m = 0; m < 5; m++) {
                        ulonglong2 wv = *(const ulonglong2*)&c_w1[c*10 + 2*m];
                        w[2*m] = wv.x; w[2*m+1] = wv.y;
                    }
                    ull a0 = 0ull;
                    #pragma unroll
                    for (int k = 0; k < 10; k++)
                        a0 = ffma2(r[k], w[k], a0);
                    float2 s0 = upk(a0);
                    const float2 bv = c_b1[c];
                    float2 pm = p1s[c*P1L + pos];
                    p1s[c*P1L + pos] =
                        make_float2(fmaxf(fmaxf(pm.x, s0.x) + bv.x, 0.f),
                                    fmaxf(fmaxf(pm.y, s0.y) + bv.y, 0.f));
                }
            }
        }
    }
    __syncthreads();

    // ---- stage 2: conv2 + relu. 2 co per thread, warp w owns ci in [8w, 8w+8)
    {
        const int lane = tid & 31;          // co pair {2*lane, 2*lane+1}
        const int w    = tid >> 5;          // ci group
        const int ci0  = 8*w;
        ull acc[20];                        // [e*10 + t]
        #pragma unroll
        for (int s = 0; s < 20; s++) acc[s] = 0ull;

        #pragma unroll 1
        for (int cc = 0; cc < 8; cc++) {
            const int ci = ci0 + cc;
            ull wk0[3], wk1[3];
            #pragma unroll
            for (int k = 0; k < 3; k++) {
                ulonglong2 wp = *(const ulonglong2*)&g_w2td[(ci*3 + k)*64 + 2*lane];
                wk0[k] = wp.x; wk1[k] = wp.y;
            }
            const ulonglong2* prow = (const ulonglong2*)&p1s[ci*P1L];
            #pragma unroll
            for (int r2 = 0; r2 < 15; r2++) {
                ulonglong2 v = prow[r2];
                const int m0 = 2*r2, m1 = 2*r2 + 1;     // m = 3t+k
                acc[m0/3]      = ffma2(v.x, wk0[m0%3], acc[m0/3]);
                acc[10 + m0/3] = ffma2(v.x, wk1[m0%3], acc[10 + m0/3]);
                acc[m1/3]      = ffma2(v.y, wk0[m1%3], acc[m1/3]);
                acc[10 + m1/3] = ffma2(v.y, wk1[m1%3], acc[10 + m1/3]);
            }
        }

        // reduce 4 warps -> warp 0 (conflict-free [slot][lane] layout)
        if (w >= 2) {
            #pragma unroll
            for (int s = 0; s < 20; s++) u.red[w-2][s][lane] = acc[s];
        }
        __syncthreads();
        if (w < 2) {
            #pragma unroll
            for (int s = 0; s < 20; s++) acc[s] = addx2(acc[s], u.red[w][s][lane]);
        }
        __syncthreads();
        if (w == 1) {
            #pragma unroll
            for (int s = 0; s < 20; s++) u.red[0][s][lane] = acc[s];
        }
        __syncthreads();
        if (w == 0) {
            const float b0 = g_b2d[2*lane].x, b1 = g_b2d[2*lane+1].x;
            #pragma unroll
            for (int t = 0; t < 10; t++) {
                float2 o0 = upk(addx2(acc[t],      u.red[0][t][lane]));
                float2 o1 = upk(addx2(acc[10 + t], u.red[0][10 + t][lane]));
                c2s[(2*lane)*11 + t]   = make_float2(fmaxf(o0.x + b0, 0.f),
                                                     fmaxf(o0.y + b0, 0.f));
                c2s[(2*lane+1)*11 + t] = make_float2(fmaxf(o1.x + b1, 0.f),
                                                     fmaxf(o1.y + b1, 0.f));
            }
        }
        __syncthreads();

        // ---- pool2 (k3,s3,pad1) + write h2 (values already >= 0)
        #pragma unroll
        for (int e = 0; e < 2; e++) {
            const int id  = tid + e*128;          // 0..255
            const int co2 = id >> 2, uu = id & 3;
            float2 m = make_float2(0.f, 0.f);
            #pragma unroll
            for (int dt = 0; dt < 3; dt++) {
                int tt = 3*uu - 1 + dt;
                if (tt >= 0 && tt < 10) {
                    float2 v = c2s[co2*11 + tt];
                    m.x = fmaxf(m.x, v.x); m.y = fmaxf(m.y, v.y);
                }
            }
            g_h2[(size_t)q*K3 + co2*4 + uu] = m;
        }
    }
}

// ---------------------------------------------------------------------------
// stage3: GEMM [BN,256] x w3^T[256,128] + bias + relu.
// Block: 32 pairs x 128 co, grid 512, 256 threads. Register-pipelined staging.
__global__ __launch_bounds__(256) void stage3k(const float* __restrict__ w3,
                                               const float* __restrict__ b3) {
    __shared__ __align__(16) float2 w3s[32*130];  // [j][co] dup-packed, pitch 130
    __shared__ __align__(16) float2 h2s[32*34];   // [j][pr], pitch 34

    const int q0  = blockIdx.x * 32;              // pair base
    const int tid = threadIdx.x;
    const int l   = tid & 31;
    const int c0  = 2*l;                          // co base (and +64)
    const int p0  = (tid >> 5) * 4;               // warp -> 4 adjacent pairs
    const int w0  = tid >> 5, jl = tid & 31;      // staging coords

    ull acc[16];
    #pragma unroll
    for (int i = 0; i < 16; i++) acc[i] = 0ull;

    float  wr[16];
    float2 hr[4];
    #pragma unroll
    for (int i = 0; i < 16; i++) wr[i] = w3[(w0 + 8*i)*256 + jl];
    #pragma unroll
    for (int i = 0; i < 4; i++)  hr[i] = g_h2[(size_t)(q0 + w0 + 8*i)*K3 + jl];

    #pragma unroll 1
    for (int c = 0; c < 8; c++) {
        if (c) __syncthreads();                   // chunk c-1 fully consumed
        #pragma unroll
        for (int i = 0; i < 16; i++)
            w3s[jl*130 + w0 + 8*i] = make_float2(wr[i], wr[i]);
        #pragma unroll
        for (int i = 0; i < 4; i++)
            h2s[jl*34 + w0 + 8*i] = hr[i];
        __syncthreads();

        if (c < 7) {                              // prefetch next chunk
            const int jc = 32*(c + 1);
            #pragma unroll
            for (int i = 0; i < 16; i++)
                wr[i] = w3[(w0 + 8*i)*256 + jc + jl];
            #pragma unroll
            for (int i = 0; i < 4; i++)
                hr[i] = g_h2[(size_t)(q0 + w0 + 8*i)*K3 + jc + jl];
        }

        #pragma unroll 4
        for (int j = 0; j < 32; j++) {
            ulonglong2 wv0 = *(const ulonglong2*)&w3s[j*130 + c0];
            ulonglong2 wv1 = *(const ulonglong2*)&w3s[j*130 + 64 + c0];
            ulonglong2 h0 = *(const ulonglong2*)&h2s[j*34 + p0];
            ulonglong2 h1 = *(const ulonglong2*)&h2s[j*34 + p0 + 2];
            acc[0]  = ffma2(h0.x, wv0.x, acc[0]);
            acc[1]  = ffma2(h0.y, wv0.x, acc[1]);
            acc[2]  = ffma2(h1.x, wv0.x, acc[2]);
            acc[3]  = ffma2(h1.y, wv0.x, acc[3]);
            acc[4]  = ffma2(h0.x, wv0.y, acc[4]);
            acc[5]  = ffma2(h0.y, wv0.y, acc[5]);
            acc[6]  = ffma2(h1.x, wv0.y, acc[6]);
            acc[7]  = ffma2(h1.y, wv0.y, acc[7]);
            acc[8]  = ffma2(h0.x, wv1.x, acc[8]);
            acc[9]  = ffma2(h0.y, wv1.x, acc[9]);
            acc[10] = ffma2(h1.x, wv1.x, acc[10]);
            acc[11] = ffma2(h1.y, wv1.x, acc[11]);
            acc[12] = ffma2(h0.x, wv1.y, acc[12]);
            acc[13] = ffma2(h0.y, wv1.y, acc[13]);
            acc[14] = ffma2(h1.x, wv1.y, acc[14]);
            acc[15] = ffma2(h1.y, wv1.y, acc[15]);
        }
    }

    const int cos[4] = { c0, c0 + 1, c0 + 64, c0 + 65 };
    #pragma unroll
    for (int m = 0; m < 4; m++) {
        const int co = cos[m];
        const float bb = b3[co];
        #pragma unroll
        for (int p = 0; p < 4; p++) {
            float2 v = upk(acc[m*4 + p]);
            const int s = 2*(q0 + p0 + p);
            g_h3[(size_t)s*C3 + co]       = fmaxf(v.x + bb, 0.f);
            g_h3[(size_t)(s+1)*C3 + co]   = fmaxf(v.y + bb, 0.f);
        }
    }
}

// ---------------------------------------------------------------------------
// headA: partial dot-products; 8 slices per batch row
__global__ __launch_bounds__(256) void headA(const float* __restrict__ wl) {
    __shared__ float red[3][256];
    const int b = blockIdx.x >> 3, s = blockIdx.x & 7;
    const int tid = threadIdx.x;
    const float4* f4  = (const float4*)(g_h3 + (size_t)b*16384);
    const float4* u0p = (const float4*)(wl);
    const float4* u1p = (const float4*)(wl + 16384);
    const float4* u2p = (const float4*)(wl + 32768);

    float a0 = 0.f, a1 = 0.f, a2 = 0.f;
    #pragma unroll
    for (int it = 0; it < 2; it++) {
        int i = s*512 + tid + it*256;
        float4 f = f4[i], u0 = u0p[i], u1 = u1p[i], u2 = u2p[i];
        a0 += f.x*u0.x + f.y*u0.y + f.z*u0.z + f.w*u0.w;
        a1 += f.x*u1.x + f.y*u1.y + f.z*u1.z + f.w*u1.w;
        a2 += f.x*u2.x + f.y*u2.y + f.z*u2.z + f.w*u2.w;
    }
    red[0][tid] = a0; red[1][tid] = a1; red[2][tid] = a2;
    __syncthreads();
    for (int st = 128; st > 0; st >>= 1) {
        if (tid < st) {
            red[0][tid] += red[0][tid + st];
            red[1][tid] += red[1][tid + st];
            red[2][tid] += red[2][tid + st];
        }
        __syncthreads();
    }
    if (tid == 0) {
        g_part[b][s][0] = red[0][0];
        g_part[b][s][1] = red[1][0];
        g_part[b][s][2] = red[2][0];
    }
}

// headB: finish logits + softmax
__global__ void headB(const float* __restrict__ bl, float* __restrict__ out) {
    const int b = blockIdx.x;
    if (threadIdx.x == 0) {
        float l0 = bl[0], l1 = bl[1], l2 = bl[2];
        #pragma unroll
        for (int s = 0; s < 8; s++) {
            l0 += g_part[b][s][0];
            l1 += g_part[b][s][1];
            l2 += g_part[b][s][2];
        }
        float mx = fmaxf(l0, fmaxf(l1, l2));
        float e0 = expf(l0 - mx), e1 = expf(l1 - mx), e2 = expf(l2 - mx);
        float inv = 1.f / (e0 + e1 + e2);
        out[b*3 + 0] = e0*inv;
        out[b*3 + 1] = e1*inv;
        out[b*3 + 2] = e2*inv;
    }
}

// ---------------------------------------------------------------------------
extern "C" void kernel_launch(void* const* d_in, const int* in_sizes, int n_in,
                              void* d_out, int out_size) {
    const float* x  = (const float*)d_in[0];
    const float* w1 = (const float*)d_in[1];
    const float* b1 = (const float*)d_in[2];
    const float* w2 = (const float*)d_in[3];
    const float* b2 = (const float*)d_in[4];
    const float* w3 = (const float*)d_in[5];
    const float* b3 = (const float*)d_in[6];
    const float* wl = (const float*)d_in[7];
    const float* bl = (const float*)d_in[8];
    float* out = (float*)d_out;

    setup_pack<<<24, 256>>>(w1, b1, w2, b2);

    // copy packed stage1 weights into __constant__ (D2D async: capturable)
    void* src_w = nullptr; void* src_b = nullptr;
    cudaGetSymbolAddress(&src_w, g_w1d);
    cudaGetSymbolAddress(&src_b, g_b1d);
    cudaMemcpyToSymbolAsync(c_w1, src_w, sizeof(float2)*C1*10, 0,
                            cudaMemcpyDeviceToDevice);
    cudaMemcpyToSymbolAsync(c_b1, src_b, sizeof(float2)*C1, 0,
                            cudaMemcpyDeviceToDevice);

    dummyk<<<1, 32>>>();     // shift ncu's fixed capture window onto stage12
    dummyk<<<1, 32>>>();
    stage12<<<BN/2, 128>>>(x);
    stage3k<<<BN/64, 256>>>(w3, b3);
    headA<<<BS*8, 256>>>(wl);
    headB<<<BS, 32>>>(bl, out);
}

// round 16
// speedup vs baseline: 1.1257x; 1.1257x over previous
#include <cuda_runtime.h>

// ---------------------------------------------------------------------------
// TimeAggNet fused pipeline, fp32 with packed f32x2 FMA (2 samples per thread)
// ---------------------------------------------------------------------------

#define BS   256
#define NN   128
#define BN   (BS*NN)      // 32768 samples
#define TLEN 1216
#define C1   32
#define P1L  30
#define C2   64
#define L2C  10
#define C3   128
#define K3   256          // C2 * 4
#define XP   46           // window pitch (float2): bank-stride 28 mod 32, 16B-aligned

typedef unsigned long long ull;

// packed-weight scratch (duplicated {w,w} for f32x2 broadcast)
__device__ __align__(16) float2 g_w1d[C1*10];
__device__ __align__(16) float2 g_b1d[C1];
__device__ __align__(16) float2 g_w2td[96*C2];   // [ci*3+k][co], dup-packed
__device__ __align__(16) float2 g_b2d[C2];
// stage1 weights on the constant port (filled via captured D2D memcpy)
__constant__ __align__(16) float2 c_w1[C1*10];
__constant__ __align__(16) float2 c_b1[C1];
// activations scratch
__device__ __align__(16) float2 g_h2[(BN/2)*K3]; // [pair q][j]
__device__ __align__(16) float  g_h3[(size_t)BN*C3];
__device__ float  g_part[BS][8][3];

__device__ __forceinline__ ull pk2(float a, float b) {
    ull r; asm("mov.b64 %0,{%1,%2};" : "=l"(r) : "f"(a), "f"(b)); return r;
}
__device__ __forceinline__ float2 upk(ull v) {
    float a, b; asm("mov.b64 {%0,%1},%2;" : "=f"(a), "=f"(b) : "l"(v));
    return make_float2(a, b);
}
__device__ __forceinline__ ull ffma2(ull a, ull b, ull c) {
    ull d; asm("fma.rn.f32x2 %0,%1,%2,%3;" : "=l"(d) : "l"(a), "l"(b), "l"(c));
    return d;
}
__device__ __forceinline__ ull addx2(ull a, ull b) {
    ull d; asm("add.rn.f32x2 %0,%1,%2;" : "=l"(d) : "l"(a), "l"(b));
    return d;
}

// ---------------------------------------------------------------------------
__global__ void setup_pack(const float* __restrict__ w1, const float* __restrict__ b1,
                           const float* __restrict__ w2, const float* __restrict__ b2) {
    int t = blockIdx.x * blockDim.x + threadIdx.x;
    if (t < C1*10) { float v = w1[t]; g_w1d[t] = make_float2(v, v); }
    if (t < C1)    { float v = b1[t]; g_b1d[t] = make_float2(v, v); }
    if (t < C2)    { float v = b2[t]; g_b2d[t] = make_float2(v, v); }
    if (t < 96*C2) {                       // transpose w2 [co][ci*3+k] -> [j][co]
        int j = t >> 6, co = t & 63;
        float v = w2[co*96 + j];
        g_w2td[t] = make_float2(v, v);
    }
}

// empty kernels to shift ncu's fixed "-s 5 -c 1" capture window (3 dummies =>
// capture lands on stage3k this round)
__global__ void dummyk() {}

// ---------------------------------------------------------------------------
// stage12: one block per sample pair, 128 threads, 6 blocks/SM.
// Private per-position windows, pitch XP=46 float2: window p slot holds
// m = 40p-1+z for z in [0,42), plus 4-entry pad that absorbs the staging
// duplicates' out-of-range writes.
__global__ __launch_bounds__(128, 6) void stage12(const float* __restrict__ x) {
    __shared__ __align__(16) union SU {
        float2 xs[P1L*XP];            // 11040 B
        ull red[2][20][32];           // 10240 B
    } u;
    __shared__ __align__(16) float2 p1s[C1*P1L];     // 7680 B
    __shared__ __align__(16) float2 c2s[C2*11];      // pitch 11: 5632 B

    const int q   = blockIdx.x;
    const int tid = threadIdx.x;
    const float* xA = x + (size_t)(2*q) * TLEN;
    const float* xB = xA + TLEN;

    // group-based staging: float4 loads; each group g covers m = 4g..4g+3.
    // primary window pa = g/10 (z = 4g-40pa+1); boundary groups (g%10 == 0 or 9)
    // also write the neighbor window; out-of-range z land in the pad.
    {
        const float4* xA4 = (const float4*)xA;
        const float4* xB4 = (const float4*)xB;
        for (int g = tid; g <= 300; g += 128) {
            float4 a = xA4[g], b = xB4[g];
            float2 v0 = make_float2(a.x, b.x), v1 = make_float2(a.y, b.y);
            float2 v2 = make_float2(a.z, b.z), v3 = make_float2(a.w, b.w);
            const int pa = g / 10;
            const int r  = g - 10*pa;
            if (pa < 30) {
                float2* d = &u.xs[XP*pa + (4*g - 40*pa + 1)];
                d[0] = v0; d[1] = v1; d[2] = v2; d[3] = v3;
            }
            if (r == 0 && pa > 0) {              // tail of window pa-1 (z=41..44)
                float2* d = &u.xs[XP*(pa-1) + 41];
                d[0] = v0; d[1] = v1; d[2] = v2; d[3] = v3;
            } else if (r == 9 && pa < 29) {      // head of window pa+1 (z=-3..0)
                float2* d = &u.xs[XP*(pa+1) - 3];
                d[0] = v0; d[1] = v1; d[2] = v2; d[3] = v3;
            }
        }
        if (tid == 0) u.xs[0] = make_float2(0.f, 0.f);   // window 0, m = -1
    }
    __syncthreads();

    // ---- stage 1: conv1 + relu + pool5, three-phase; weights via const port
    {
        const int pos = tid & 31, cg = tid >> 5;
        if (pos < P1L) {
            const float2* xw = &u.xs[XP*pos];
            // phase 0: windows j=0,1 (z 0..17)
            {
                ull r[18];
                const ulonglong2* bp = (const ulonglong2*)xw;
                #pragma unroll
                for (int z = 0; z < 9; z++) {
                    ulonglong2 v = bp[z]; r[2*z] = v.x; r[2*z+1] = v.y;
                }
                #pragma unroll 1
                for (int cc = 0; cc < 8; cc++) {
                    const int c = cg*8 + cc;
                    ull w[10];
                    #pragma unroll
                    for (int m = 0; m < 5; m++) {
                        ulonglong2 wv = *(const ulonglong2*)&c_w1[c*10 + 2*m];
                        w[2*m] = wv.x; w[2*m+1] = wv.y;
                    }
                    ull a0 = 0ull, a1 = 0ull;
                    #pragma unroll
                    for (int k = 0; k < 10; k++) {
                        a0 = ffma2(r[k],     w[k], a0);
                        a1 = ffma2(r[8 + k], w[k], a1);
                    }
                    float2 s0 = upk(a0), s1 = upk(a1);
                    p1s[c*P1L + pos] = make_float2(fmaxf(s0.x, s1.x),
                                                   fmaxf(s0.y, s1.y));
                }
            }
            // phase 1: windows j=2,3 (z 16..33)
            {
                ull r[18];
                const ulonglong2* bp = (const ulonglong2*)(xw + 16);
                #pragma unroll
                for (int z = 0; z < 9; z++) {
                    ulonglong2 v = bp[z]; r[2*z] = v.x; r[2*z+1] = v.y;
                }
                #pragma unroll 1
                for (int cc = 0; cc < 8; cc++) {
                    const int c = cg*8 + cc;
                    ull w[10];
                    #pragma unroll
                    for (int m = 0; m < 5; m++) {
                        ulonglong2 wv = *(const ulonglong2*)&c_w1[c*10 + 2*m];
                        w[2*m] = wv.x; w[2*m+1] = wv.y;
                    }
                    ull a0 = 0ull, a1 = 0ull;
                    #pragma unroll
                    for (int k = 0; k < 10; k++) {
                        a0 = ffma2(r[k],     w[k], a0);   // window 2
                        a1 = ffma2(r[8 + k], w[k], a1);   // window 3
                    }
                    float2 s0 = upk(a0), s1 = upk(a1);
                    float2 pm = p1s[c*P1L + pos];
                    p1s[c*P1L + pos] =
                        make_float2(fmaxf(pm.x, fmaxf(s0.x, s1.x)),
                                    fmaxf(pm.y, fmaxf(s0.y, s1.y)));
                }
            }
            // phase 2: window j=4 (z 32..41), + bias + relu
            {
                ull r[10];
                const ulonglong2* bp = (const ulonglong2*)(xw + 32);
                #pragma unroll
                for (int z = 0; z < 5; z++) {
                    ulonglong2 v = bp[z]; r[2*z] = v.x; r[2*z+1] = v.y;
                }
                #pragma unroll 1
                for (int cc = 0; cc < 8; cc++) {
                    const int c = cg*8 + cc;
                    ull w[10];
                    #pragma unroll
                    for (int m = 0; m < 5; m++) {
                        ulonglong2 wv = *(const ulonglong2*)&c_w1[c*10 + 2*m];
                        w[2*m] = wv.x; w[2*m+1] = wv.y;
                    }
                    ull a0 = 0ull;
                    #pragma unroll
                    for (int k = 0; k < 10; k++)
                        a0 = ffma2(r[k], w[k], a0);
                    float2 s0 = upk(a0);
                    const float2 bv = c_b1[c];
                    float2 pm = p1s[c*P1L + pos];
                    p1s[c*P1L + pos] =
                        make_float2(fmaxf(fmaxf(pm.x, s0.x) + bv.x, 0.f),
                                    fmaxf(fmaxf(pm.y, s0.y) + bv.y, 0.f));
                }
            }
        }
    }
    __syncthreads();

    // ---- stage 2: conv2 + relu. 2 co per thread, warp w owns ci in [8w, 8w+8)
    {
        const int lane = tid & 31;          // co pair {2*lane, 2*lane+1}
        const int w    = tid >> 5;          // ci group
        const int ci0  = 8*w;
        ull acc[20];                        // [e*10 + t]
        #pragma unroll
        for (int s = 0; s < 20; s++) acc[s] = 0ull;

        #pragma unroll 1
        for (int cc = 0; cc < 8; cc++) {
            const int ci = ci0 + cc;
            ull wk0[3], wk1[3];
            #pragma unroll
            for (int k = 0; k < 3; k++) {
                ulonglong2 wp = *(const ulonglong2*)&g_w2td[(ci*3 + k)*64 + 2*lane];
                wk0[k] = wp.x; wk1[k] = wp.y;
            }
            const ulonglong2* prow = (const ulonglong2*)&p1s[ci*P1L];
            #pragma unroll
            for (int r2 = 0; r2 < 15; r2++) {
                ulonglong2 v = prow[r2];
                const int m0 = 2*r2, m1 = 2*r2 + 1;     // m = 3t+k
                acc[m0/3]      = ffma2(v.x, wk0[m0%3], acc[m0/3]);
                acc[10 + m0/3] = ffma2(v.x, wk1[m0%3], acc[10 + m0/3]);
                acc[m1/3]      = ffma2(v.y, wk0[m1%3], acc[m1/3]);
                acc[10 + m1/3] = ffma2(v.y, wk1[m1%3], acc[10 + m1/3]);
            }
        }

        // reduce 4 warps -> warp 0 (conflict-free [slot][lane] layout)
        if (w >= 2) {
            #pragma unroll
            for (int s = 0; s < 20; s++) u.red[w-2][s][lane] = acc[s];
        }
        __syncthreads();
        if (w < 2) {
            #pragma unroll
            for (int s = 0; s < 20; s++) acc[s] = addx2(acc[s], u.red[w][s][lane]);
        }
        __syncthreads();
        if (w == 1) {
            #pragma unroll
            for (int s = 0; s < 20; s++) u.red[0][s][lane] = acc[s];
        }
        __syncthreads();
        if (w == 0) {
            const float b0 = g_b2d[2*lane].x, b1 = g_b2d[2*lane+1].x;
            #pragma unroll
            for (int t = 0; t < 10; t++) {
                float2 o0 = upk(addx2(acc[t],      u.red[0][t][lane]));
                float2 o1 = upk(addx2(acc[10 + t], u.red[0][10 + t][lane]));
                c2s[(2*lane)*11 + t]   = make_float2(fmaxf(o0.x + b0, 0.f),
                                                     fmaxf(o0.y + b0, 0.f));
                c2s[(2*lane+1)*11 + t] = make_float2(fmaxf(o1.x + b1, 0.f),
                                                     fmaxf(o1.y + b1, 0.f));
            }
        }
        __syncthreads();

        // ---- pool2 (k3,s3,pad1) + write h2 (values already >= 0)
        #pragma unroll
        for (int e = 0; e < 2; e++) {
            const int id  = tid + e*128;          // 0..255
            const int co2 = id >> 2, uu = id & 3;
            float2 m = make_float2(0.f, 0.f);
            #pragma unroll
            for (int dt = 0; dt < 3; dt++) {
                int tt = 3*uu - 1 + dt;
                if (tt >= 0 && tt < 10) {
                    float2 v = c2s[co2*11 + tt];
                    m.x = fmaxf(m.x, v.x); m.y = fmaxf(m.y, v.y);
                }
            }
            g_h2[(size_t)q*K3 + co2*4 + uu] = m;
        }
    }
}

// ---------------------------------------------------------------------------
// stage3: GEMM [BN,256] x w3^T[256,128] + bias + relu.
// Block: 32 pairs x 128 co, grid 512, 256 threads. Register-pipelined staging.
__global__ __launch_bounds__(256) void stage3k(const float* __restrict__ w3,
                                               const float* __restrict__ b3) {
    __shared__ __align__(16) float2 w3s[32*130];  // [j][co] dup-packed, pitch 130
    __shared__ __align__(16) float2 h2s[32*34];   // [j][pr], pitch 34

    const int q0  = blockIdx.x * 32;              // pair base
    const int tid = threadIdx.x;
    const int l   = tid & 31;
    const int c0  = 2*l;                          // co base (and +64)
    const int p0  = (tid >> 5) * 4;               // warp -> 4 adjacent pairs
    const int w0  = tid >> 5, jl = tid & 31;      // staging coords

    ull acc[16];
    #pragma unroll
    for (int i = 0; i < 16; i++) acc[i] = 0ull;

    float  wr[16];
    float2 hr[4];
    #pragma unroll
    for (int i = 0; i < 16; i++) wr[i] = w3[(w0 + 8*i)*256 + jl];
    #pragma unroll
    for (int i = 0; i < 4; i++)  hr[i] = g_h2[(size_t)(q0 + w0 + 8*i)*K3 + jl];

    #pragma unroll 1
    for (int c = 0; c < 8; c++) {
        if (c) __syncthreads();                   // chunk c-1 fully consumed
        #pragma unroll
        for (int i = 0; i < 16; i++)
            w3s[jl*130 + w0 + 8*i] = make_float2(wr[i], wr[i]);
        #pragma unroll
        for (int i = 0; i < 4; i++)
            h2s[jl*34 + w0 + 8*i] = hr[i];
        __syncthreads();

        if (c < 7) {                              // prefetch next chunk
            const int jc = 32*(c + 1);
            #pragma unroll
            for (int i = 0; i < 16; i++)
                wr[i] = w3[(w0 + 8*i)*256 + jc + jl];
            #pragma unroll
            for (int i = 0; i < 4; i++)
                hr[i] = g_h2[(size_t)(q0 + w0 + 8*i)*K3 + jc + jl];
        }

        #pragma unroll 4
        for (int j = 0; j < 32; j++) {
            ulonglong2 wv0 = *(const ulonglong2*)&w3s[j*130 + c0];
            ulonglong2 wv1 = *(const ulonglong2*)&w3s[j*130 + 64 + c0];
            ulonglong2 h0 = *(const ulonglong2*)&h2s[j*34 + p0];
            ulonglong2 h1 = *(const ulonglong2*)&h2s[j*34 + p0 + 2];
            acc[0]  = ffma2(h0.x, wv0.x, acc[0]);
            acc[1]  = ffma2(h0.y, wv0.x, acc[1]);
            acc[2]  = ffma2(h1.x, wv0.x, acc[2]);
            acc[3]  = ffma2(h1.y, wv0.x, acc[3]);
            acc[4]  = ffma2(h0.x, wv0.y, acc[4]);
            acc[5]  = ffma2(h0.y, wv0.y, acc[5]);
            acc[6]  = ffma2(h1.x, wv0.y, acc[6]);
            acc[7]  = ffma2(h1.y, wv0.y, acc[7]);
            acc[8]  = ffma2(h0.x, wv1.x, acc[8]);
            acc[9]  = ffma2(h0.y, wv1.x, acc[9]);
            acc[10] = ffma2(h1.x, wv1.x, acc[10]);
            acc[11] = ffma2(h1.y, wv1.x, acc[11]);
            acc[12] = ffma2(h0.x, wv1.y, acc[12]);
            acc[13] = ffma2(h0.y, wv1.y, acc[13]);
            acc[14] = ffma2(h1.x, wv1.y, acc[14]);
            acc[15] = ffma2(h1.y, wv1.y, acc[15]);
        }
    }

    const int cos[4] = { c0, c0 + 1, c0 + 64, c0 + 65 };
    #pragma unroll
    for (int m = 0; m < 4; m++) {
        const int co = cos[m];
        const float bb = b3[co];
        #pragma unroll
        for (int p = 0; p < 4; p++) {
            float2 v = upk(acc[m*4 + p]);
            const int s = 2*(q0 + p0 + p);
            g_h3[(size_t)s*C3 + co]       = fmaxf(v.x + bb, 0.f);
            g_h3[(size_t)(s+1)*C3 + co]   = fmaxf(v.y + bb, 0.f);
        }
    }
}

// ---------------------------------------------------------------------------
// headA: partial dot-products; 8 slices per batch row
__global__ __launch_bounds__(256) void headA(const float* __restrict__ wl) {
    __shared__ float red[3][256];
    const int b = blockIdx.x >> 3, s = blockIdx.x & 7;
    const int tid = threadIdx.x;
    const float4* f4  = (const float4*)(g_h3 + (size_t)b*16384);
    const float4* u0p = (const float4*)(wl);
    const float4* u1p = (const float4*)(wl + 16384);
    const float4* u2p = (const float4*)(wl + 32768);

    float a0 = 0.f, a1 = 0.f, a2 = 0.f;
    #pragma unroll
    for (int it = 0; it < 2; it++) {
        int i = s*512 + tid + it*256;
        float4 f = f4[i], u0 = u0p[i], u1 = u1p[i], u2 = u2p[i];
        a0 += f.x*u0.x + f.y*u0.y + f.z*u0.z + f.w*u0.w;
        a1 += f.x*u1.x + f.y*u1.y + f.z*u1.z + f.w*u1.w;
        a2 += f.x*u2.x + f.y*u2.y + f.z*u2.z + f.w*u2.w;
    }
    red[0][tid] = a0; red[1][tid] = a1; red[2][tid] = a2;
    __syncthreads();
    for (int st = 128; st > 0; st >>= 1) {
        if (tid < st) {
            red[0][tid] += red[0][tid + st];
            red[1][tid] += red[1][tid + st];
            red[2][tid] += red[2][tid + st];
        }
        __syncthreads();
    }
    if (tid == 0) {
        g_part[b][s][0] = red[0][0];
        g_part[b][s][1] = red[1][0];
        g_part[b][s][2] = red[2][0];
    }
}

// headB: finish logits + softmax
__global__ void headB(const float* __restrict__ bl, float* __restrict__ out) {
    const int b = blockIdx.x;
    if (threadIdx.x == 0) {
        float l0 = bl[0], l1 = bl[1], l2 = bl[2];
        #pragma unroll
        for (int s = 0; s < 8; s++) {
            l0 += g_part[b][s][0];
            l1 += g_part[b][s][1];
            l2 += g_part[b][s][2];
        }
        float mx = fmaxf(l0, fmaxf(l1, l2));
        float e0 = expf(l0 - mx), e1 = expf(l1 - mx), e2 = expf(l2 - mx);
        float inv = 1.f / (e0 + e1 + e2);
        out[b*3 + 0] = e0*inv;
        out[b*3 + 1] = e1*inv;
        out[b*3 + 2] = e2*inv;
    }
}

// ---------------------------------------------------------------------------
extern "C" void kernel_launch(void* const* d_in, const int* in_sizes, int n_in,
                              void* d_out, int out_size) {
    const float* x  = (const float*)d_in[0];
    const float* w1 = (const float*)d_in[1];
    const float* b1 = (const float*)d_in[2];
    const float* w2 = (const float*)d_in[3];
    const float* b2 = (const float*)d_in[4];
    const float* w3 = (const float*)d_in[5];
    const float* b3 = (const float*)d_in[6];
    const float* wl = (const float*)d_in[7];
    const float* bl = (const float*)d_in[8];
    float* out = (float*)d_out;

    setup_pack<<<24, 256>>>(w1, b1, w2, b2);

    // copy packed stage1 weights into __constant__ (D2D async: capturable)
    void* src_w = nullptr; void* src_b = nullptr;
    cudaGetSymbolAddress(&src_w, g_w1d);
    cudaGetSymbolAddress(&src_b, g_b1d);
    cudaMemcpyToSymbolAsync(c_w1, src_w, sizeof(float2)*C1*10, 0,
                            cudaMemcpyDeviceToDevice);
    cudaMemcpyToSymbolAsync(c_b1, src_b, sizeof(float2)*C1, 0,
                            cudaMemcpyDeviceToDevice);

    dummyk<<<1, 32>>>();     // 3 dummies: ncu capture window lands on stage3k
    dummyk<<<1, 32>>>();
    dummyk<<<1, 32>>>();
    stage12<<<BN/2, 128>>>(x);
    stage3k<<<BN/64, 256>>>(w3, b3);
    headA<<<BS*8, 256>>>(wl);
    headB<<<BS, 32>>>(bl, out);
}